// round 2
// baseline (speedup 1.0000x reference)
#include <cuda_runtime.h>
#include <cstdint>

#define TOT    400000
#define NPTS   50000
#define NBLK   5

typedef unsigned long long ull;

// Per-batch conditioning: cond[b][i][h] = task_feature[b] @ fc_c_W[i][64:576,:] + fc_c_b[i]
__device__ float g_cond[8 * NBLK * 64];

// ---------- packed f32x2 helpers ----------
__device__ __forceinline__ ull dup2(float x) {
    ull r; asm("mov.b64 %0, {%1, %1};" : "=l"(r) : "f"(x)); return r;
}
__device__ __forceinline__ float2 unpk(ull a) {
    float2 f; asm("mov.b64 {%0, %1}, %2;" : "=f"(f.x), "=f"(f.y) : "l"(a)); return f;
}
__device__ __forceinline__ void fma2(ull &a, ull x, ull w) {
    asm("fma.rn.f32x2 %0, %1, %2, %0;" : "+l"(a) : "l"(x), "l"(w));
}
__device__ __forceinline__ void add2(ull &a, ull b) {
    asm("add.rn.f32x2 %0, %0, %1;" : "+l"(a) : "l"(b));
}

// ---------- shared memory layout (floats) ----------
#define OFF_W     0        // 3 * 64*64 = 12288 (Wc, W0, W1 for current block)
#define OFF_B0    12288    // 64
#define OFF_B1    12352    // 64
#define OFF_PW    12416    // 192  (fc_p_W [3][64])
#define OFF_PB    12608    // 64
#define OFF_OW    12672    // 768  (fc_out_W [64][12])
#define OFF_OB    13440    // 12 (+4 pad)
#define OFF_COND  13456    // 8*5*64 = 2560
#define OFF_C     16016    // 256 * 65 = 16640 (point codes, stride 65 = conflict-free)
#define SM_FLOATS 32656
#define SM_BYTES  (SM_FLOATS * 4)

// ---------- conditioning precompute ----------
__global__ void cond_kernel(const float* __restrict__ tf,
                            const float* __restrict__ fc_c_W,
                            const float* __restrict__ fc_c_b) {
    int bi = blockIdx.x;          // b*5 + i
    int b  = bi / NBLK, i = bi % NBLK;
    int h  = threadIdx.x & 63, g = threadIdx.x >> 6;   // 4 groups over t
    const float* W = fc_c_W + (size_t)i * 576 * 64 + 64 * 64 + h;
    const float* t = tf + b * 512;
    float acc = 0.f;
    int k0 = g * 128;
    #pragma unroll 8
    for (int k = k0; k < k0 + 128; k++) acc += t[k] * W[(size_t)k * 64];
    __shared__ float red[256];
    red[threadIdx.x] = acc;
    __syncthreads();
    if (g == 0) {
        float s = red[h] + red[h + 64] + red[h + 128] + red[h + 192] + fc_c_b[i * 64 + h];
        g_cond[bi * 64 + h] = s;
    }
}

// ---------- main kernel: one thread per point ----------
__global__ __launch_bounds__(256, 1)
void mlp_kernel(const float* __restrict__ p, const float* __restrict__ c,
                const float* __restrict__ fc_p_W, const float* __restrict__ fc_p_b,
                const float* __restrict__ fc_c_W,
                const float* __restrict__ blk0_W, const float* __restrict__ blk0_b,
                const float* __restrict__ blk1_W, const float* __restrict__ blk1_b,
                const float* __restrict__ fc_out_W, const float* __restrict__ fc_out_b,
                float* __restrict__ out) {
    extern __shared__ float sm[];
    const int tid  = threadIdx.x;
    const int base = blockIdx.x * 256;
    const int idx  = base + tid;
    const bool active = idx < TOT;

    // one-time loads
    for (int w = tid; w < 192; w += 256) sm[OFF_PW + w] = fc_p_W[w];
    if (tid < 64)  sm[OFF_PB + tid] = fc_p_b[tid];
    for (int w = tid; w < 768; w += 256) sm[OFF_OW + w] = fc_out_W[w];
    if (tid < 12)  sm[OFF_OB + tid] = fc_out_b[tid];
    for (int w = tid; w < 8 * NBLK * 64; w += 256) sm[OFF_COND + w] = g_cond[w];

    // stage this chunk's point codes into shared (coalesced, stride-65 layout)
    {
        int npts = TOT - base; if (npts > 256) npts = 256;
        int nf4 = npts << 4;
        const float4* src = (const float4*)(c + (size_t)base * 64);
        for (int w = tid; w < nf4; w += 256) {
            float4 v = src[w];
            int pt = w >> 4, e = (w & 15) << 2;
            float* d = sm + OFF_C + pt * 65 + e;
            d[0] = v.x; d[1] = v.y; d[2] = v.z; d[3] = v.w;
        }
        // zero-fill codes of inactive tail points so they never read garbage
        for (int w = (npts << 4) + tid; w < (256 << 4); w += 256) {
            int pt = w >> 4, e = (w & 15) << 2;
            float* d = sm + OFF_C + pt * 65 + e;
            d[0] = 0.f; d[1] = 0.f; d[2] = 0.f; d[3] = 0.f;
        }
    }
    __syncthreads();

    // net = p @ fc_p_W + fc_p_b
    ull net[32];
    {
        const ull* pb = (const ull*)(sm + OFF_PB);
        #pragma unroll
        for (int j = 0; j < 32; j++) net[j] = pb[j];
        float p0 = 0.f, p1 = 0.f, p2 = 0.f;
        if (active) {
            p0 = p[(size_t)idx * 3 + 0];
            p1 = p[(size_t)idx * 3 + 1];
            p2 = p[(size_t)idx * 3 + 2];
        }
        ull d0 = dup2(p0), d1 = dup2(p1), d2 = dup2(p2);
        const ulonglong2* r0 = (const ulonglong2*)(sm + OFF_PW);
        const ulonglong2* r1 = (const ulonglong2*)(sm + OFF_PW + 64);
        const ulonglong2* r2 = (const ulonglong2*)(sm + OFF_PW + 128);
        #pragma unroll
        for (int j = 0; j < 16; j++) {
            ulonglong2 w0 = r0[j]; fma2(net[2*j], d0, w0.x); fma2(net[2*j+1], d0, w0.y);
            ulonglong2 w1 = r1[j]; fma2(net[2*j], d1, w1.x); fma2(net[2*j+1], d1, w1.y);
            ulonglong2 w2 = r2[j]; fma2(net[2*j], d2, w2.x); fma2(net[2*j+1], d2, w2.y);
        }
    }

    int b = idx / NPTS; if (b > 7) b = 7;
    const float* myc = sm + OFF_C + tid * 65;

    #pragma unroll 1
    for (int i = 0; i < NBLK; i++) {
        __syncthreads();
        // cooperative load of this block's weights (Wc = first 64 rows of fc_c_W[i])
        {
            const float4* wc = (const float4*)(fc_c_W + (size_t)i * 576 * 64);
            const float4* w0 = (const float4*)(blk0_W + (size_t)i * 4096);
            const float4* w1 = (const float4*)(blk1_W + (size_t)i * 4096);
            float4* dW = (float4*)(sm + OFF_W);
            #pragma unroll
            for (int w = 0; w < 4; w++) {
                dW[tid + w * 256]        = wc[tid + w * 256];
                dW[1024 + tid + w * 256] = w0[tid + w * 256];
                dW[2048 + tid + w * 256] = w1[tid + w * 256];
            }
            if (tid < 64) {
                sm[OFF_B0 + tid] = blk0_b[i * 64 + tid];
                sm[OFF_B1 + tid] = blk1_b[i * 64 + tid];
            }
        }
        __syncthreads();

        // net += c @ Wc + cond[b][i]     (k-loop rolled: x comes from shared)
        #pragma unroll 4
        for (int k = 0; k < 64; k++) {
            ull xd = dup2(myc[k]);
            const ulonglong2* wr = (const ulonglong2*)(sm + OFF_W + (k << 6));
            #pragma unroll
            for (int j = 0; j < 16; j++) {
                ulonglong2 wv = wr[j];
                fma2(net[2*j], xd, wv.x);
                fma2(net[2*j+1], xd, wv.y);
            }
        }
        {
            const ull* cd = (const ull*)(sm + OFF_COND + ((b * NBLK + i) << 6));
            #pragma unroll
            for (int j = 0; j < 32; j++) add2(net[j], cd[j]);
        }

        // h = relu(net) @ W0 + b0
        ull hh[32];
        {
            const ull* b0 = (const ull*)(sm + OFF_B0);
            #pragma unroll
            for (int j = 0; j < 32; j++) hh[j] = b0[j];
            #pragma unroll
            for (int k2 = 0; k2 < 32; k2++) {
                float2 xp = unpk(net[k2]);
                ull xd0 = dup2(fmaxf(xp.x, 0.f));
                ull xd1 = dup2(fmaxf(xp.y, 0.f));
                const ulonglong2* wr0 = (const ulonglong2*)(sm + OFF_W + 4096 + (k2 << 7));
                const ulonglong2* wr1 = (const ulonglong2*)(sm + OFF_W + 4096 + (k2 << 7) + 64);
                #pragma unroll
                for (int j = 0; j < 16; j++) {
                    ulonglong2 wv = wr0[j];
                    fma2(hh[2*j], xd0, wv.x); fma2(hh[2*j+1], xd0, wv.y);
                }
                #pragma unroll
                for (int j = 0; j < 16; j++) {
                    ulonglong2 wv = wr1[j];
                    fma2(hh[2*j], xd1, wv.x); fma2(hh[2*j+1], xd1, wv.y);
                }
            }
        }

        // net += b1 + relu(h) @ W1
        {
            const ull* b1 = (const ull*)(sm + OFF_B1);
            #pragma unroll
            for (int j = 0; j < 32; j++) add2(net[j], b1[j]);
            #pragma unroll
            for (int k2 = 0; k2 < 32; k2++) {
                float2 xp = unpk(hh[k2]);
                ull xd0 = dup2(fmaxf(xp.x, 0.f));
                ull xd1 = dup2(fmaxf(xp.y, 0.f));
                const ulonglong2* wr0 = (const ulonglong2*)(sm + OFF_W + 8192 + (k2 << 7));
                const ulonglong2* wr1 = (const ulonglong2*)(sm + OFF_W + 8192 + (k2 << 7) + 64);
                #pragma unroll
                for (int j = 0; j < 16; j++) {
                    ulonglong2 wv = wr0[j];
                    fma2(net[2*j], xd0, wv.x); fma2(net[2*j+1], xd0, wv.y);
                }
                #pragma unroll
                for (int j = 0; j < 16; j++) {
                    ulonglong2 wv = wr1[j];
                    fma2(net[2*j], xd1, wv.x); fma2(net[2*j+1], xd1, wv.y);
                }
            }
        }
    }

    // out = relu(net) @ fc_out_W + fc_out_b   (12 outputs = 6 packed accs)
    {
        ull o[6];
        const ull* ob = (const ull*)(sm + OFF_OB);
        #pragma unroll
        for (int j = 0; j < 6; j++) o[j] = ob[j];
        #pragma unroll
        for (int k2 = 0; k2 < 32; k2++) {
            float2 xp = unpk(net[k2]);
            ull xd0 = dup2(fmaxf(xp.x, 0.f));
            ull xd1 = dup2(fmaxf(xp.y, 0.f));
            const ull* wr0 = (const ull*)(sm + OFF_OW + k2 * 24);
            const ull* wr1 = (const ull*)(sm + OFF_OW + k2 * 24 + 12);
            #pragma unroll
            for (int j = 0; j < 6; j++) fma2(o[j], xd0, wr0[j]);
            #pragma unroll
            for (int j = 0; j < 6; j++) fma2(o[j], xd1, wr1[j]);
        }
        if (active) {
            float2 f0 = unpk(o[0]), f1 = unpk(o[1]), f2 = unpk(o[2]);
            float2 f3 = unpk(o[3]), f4 = unpk(o[4]), f5 = unpk(o[5]);
            float4* dst = (float4*)(out + (size_t)idx * 12);
            dst[0] = make_float4(f0.x, f0.y, f1.x, f1.y);
            dst[1] = make_float4(f2.x, f2.y, f3.x, f3.y);
            dst[2] = make_float4(f4.x, f4.y, f5.x, f5.y);
        }
    }
}

extern "C" void kernel_launch(void* const* d_in, const int* in_sizes, int n_in,
                              void* d_out, int out_size) {
    const float* p        = (const float*)d_in[0];
    const float* c        = (const float*)d_in[1];
    const float* tf       = (const float*)d_in[2];
    const float* fc_p_W   = (const float*)d_in[3];
    const float* fc_p_b   = (const float*)d_in[4];
    const float* fc_c_W   = (const float*)d_in[5];
    const float* fc_c_b   = (const float*)d_in[6];
    const float* blk0_W   = (const float*)d_in[7];
    const float* blk0_b   = (const float*)d_in[8];
    const float* blk1_W   = (const float*)d_in[9];
    const float* blk1_b   = (const float*)d_in[10];
    const float* fc_out_W = (const float*)d_in[11];
    const float* fc_out_b = (const float*)d_in[12];
    float* out = (float*)d_out;

    cudaFuncSetAttribute(mlp_kernel, cudaFuncAttributeMaxDynamicSharedMemorySize, SM_BYTES);

    cond_kernel<<<8 * NBLK, 256>>>(tf, fc_c_W, fc_c_b);

    int grid = (TOT + 255) / 256;   // 1563 CTAs, one 256-point chunk each
    mlp_kernel<<<grid, 256, SM_BYTES>>>(p, c, fc_p_W, fc_p_b, fc_c_W,
                                        blk0_W, blk0_b, blk1_W, blk1_b,
                                        fc_out_W, fc_out_b, out);
}